// round 15
// baseline (speedup 1.0000x reference)
#include <cuda_runtime.h>
#include <cuda_fp16.h>
#include <cstdint>
#include <cstddef>

// ================= problem =================
// x:(16,128,112,112)f32  weight:(128,128,3,3)  P:(2,128,128,3,3)  bias:(128)
// out:(16,128,112,112) = conv(x, scatter(weight,P) 9x9, pad 4) + bias

#define TAPS 81

// K2 fragment layout: [tap][cichunk(4)][cotile16(8)][kk(2)][lane(32)] uint4
// (2048 uint4 / tap). Lane's uint4 = m16k16 fp16 A-frag regs {a0,a1,a2,a3}:
//   lane=(row&7)*4+((col&7)>>1), reg=(row>>3)+((col>>3)<<1), half=(col&1)
__device__ uint4 g_K2f[TAPS * 4 * 8 * 2 * 32];

// x transposed to f16 NHWC with baked-in halo: [b][h+4 (120)][w+4 (120)][ci 128]
__device__ uint4 g_xT[16 * 120 * 120 * 128 / 8];

__device__ __forceinline__ uint32_t smem_u32(const void* p) {
    uint32_t a;
    asm("{ .reg .u64 t; cvta.to.shared.u64 t, %1; cvt.u32.u64 %0, t; }" : "=r"(a) : "l"(p));
    return a;
}

#define LDSM4(rv, addr)                                                          \
    asm volatile("ldmatrix.sync.aligned.m8n8.x4.shared.b16 {%0,%1,%2,%3}, [%4];" \
        : "=r"((rv)[0]), "=r"((rv)[1]), "=r"((rv)[2]), "=r"((rv)[3]) : "r"(addr))

#define LDSM2(rv, addr)                                                      \
    asm volatile("ldmatrix.sync.aligned.m8n8.x2.shared.b16 {%0,%1}, [%2];"   \
        : "=r"((rv)[0]), "=r"((rv)[1]) : "r"(addr))

#define HMMA(d, a, b0, b1)                                                   \
    asm volatile("mma.sync.aligned.m16n8k16.row.col.f32.f16.f16.f32 "        \
        "{%0,%1,%2,%3}, {%4,%5,%6,%7}, {%8,%9}, {%0,%1,%2,%3};"              \
        : "+f"((d)[0]), "+f"((d)[1]), "+f"((d)[2]), "+f"((d)[3])             \
        : "r"((a)[0]), "r"((a)[1]), "r"((a)[2]), "r"((a)[3]),                \
          "r"(b0), "r"(b1))

#define CP_ASYNC16(sdst, gsrc)                                               \
    asm volatile("cp.async.cg.shared.global [%0], [%1], 16;"                 \
        :: "r"(sdst), "l"(gsrc) : "memory")
#define CP_COMMIT()   asm volatile("cp.async.commit_group;" ::: "memory")
#define CP_WAIT0()    asm volatile("cp.async.wait_group 0;" ::: "memory")

// ======== merged pre-pass: transpose x -> f16 NHWC (halo zeroed) + build_K ========
// grid 2048: blocks 0..1919 transpose (b = blk/120, hp = blk%120);
//            blocks 1920..2047 scatter weights for co = blk-1920.
// Dynamic smem reused by both paths (41472 B).
__global__ void prep(const float* __restrict__ x,
                     const float* __restrict__ weight, const float* __restrict__ P) {
    extern __shared__ char psm[];
    const int tid = threadIdx.x;

    if (blockIdx.x < 1920) {
        __half* s = (__half*)psm;              // [112][130]
        const int b  = blockIdx.x / 120;
        const int hp = blockIdx.x - b * 120;
        __half* xt = (__half*)g_xT + (((size_t)b * 120 + hp) * 120) * 128;

        if (hp < 4 || hp >= 116) {             // full halo row
            uint4 z = make_uint4(0, 0, 0, 0);
            for (int u = tid; u < 1920; u += 256) ((uint4*)xt)[u] = z;
            return;
        }
        const int hh = hp - 4;

        const float* xb = x + ((size_t)b * 128) * 12544 + hh * 112;
        for (int u = tid; u < 128 * 112; u += 256) {
            int ci = u / 112, w = u - ci * 112;
            s[w * 130 + ci] = __float2half_rn(xb[(size_t)ci * 12544 + w]);
        }
        {   // w halo: pixels 0..3 and 116..119
            uint4 z = make_uint4(0, 0, 0, 0);
            for (int u = tid; u < 128; u += 256) {
                int side = u >> 6, pw = (u >> 4) & 3, seg = u & 15;
                ((uint4*)(xt + (size_t)(side * 116 + pw) * 128))[seg] = z;
            }
        }
        __syncthreads();

        __half* xti = xt + 4 * 128;
        for (int u = tid; u < 112 * 64; u += 256) {
            int w = u >> 6, cp = u & 63;
            __half2 v = make_half2(s[w * 130 + 2 * cp], s[w * 130 + 2 * cp + 1]);
            *(__half2*)(xti + (size_t)w * 128 + 2 * cp) = v;
        }
        return;
    }

    // ---- build_K path ----
    if (tid >= 128) return;
    float (*sK)[81] = (float(*)[81])psm;       // [128][81]
    const int co = blockIdx.x - 1920;
    const int ci = tid;

    #pragma unroll
    for (int i = 0; i < 81; i++) sK[ci][i] = 0.f;

    const float* P0 = P;
    const float* P1 = P + 128 * 128 * 9;

    #pragma unroll
    for (int kh = 0; kh < 3; kh++) {
        #pragma unroll
        for (int kw = 0; kw < 3; kw++) {
            int widx = ((co * 128 + ci) * 3 + kh) * 3 + kw;
            float w  = weight[widx];
            float ph = (float)(kh * 4) + P0[widx];
            float pw = (float)(kw * 4) + P1[widx];
            ph = fminf(fmaxf(ph, 0.f), 8.f);
            pw = fminf(fmaxf(pw, 0.f), 8.f);
            float fh = floorf(ph), fw = floorf(pw);
            float rh = ph - fh,    rw = pw - fw;
            int ih = (int)fh, iw = (int)fw;
            int ih1 = min(ih + 1, 8), iw1 = min(iw + 1, 8);
            sK[ci][ih  * 9 + iw ] += w * (1.f - rh) * (1.f - rw);
            sK[ci][ih1 * 9 + iw ] += w * rh         * (1.f - rw);
            sK[ci][ih  * 9 + iw1] += w * (1.f - rh) * rw;
            sK[ci][ih1 * 9 + iw1] += w * rh         * rw;
        }
    }
    __syncwarp();

    const int c     = ci >> 5;
    const int kk    = (ci >> 4) & 1;
    const int col   = ci & 15;
    const int iglob = co >> 4;
    const int row   = co & 15;
    const int lane  = (row & 7) * 4 + ((col & 7) >> 1);
    const int reg   = (row >> 3) + ((col >> 3) << 1);
    __half* gh = (__half*)g_K2f;
    const size_t slot = ((((size_t)c * 8 + iglob) * 2 + kk) * 32 + lane) * 8 + reg * 2 + (col & 1);
    for (int tap = 0; tap < 81; tap++)
        gh[(size_t)tap * 16384 + slot] = __float2half_rn(sK[ci][tap]);
}

// ================= stage 2: fp16 implicit-GEMM conv (MAIN, tiles 0..887) =================
// EXACT round-10 structure (proven): block = 128 co x (4 rows x 56 w), 8 warps,
// warp tile 64co x 56px, K in 4 chunks of 32, A reg-double-buffered from
// fragment-layout LDG, B double-buffered cp.async from f16 NHWC xT.
// Grid 888 = exactly 6 full waves on 148 SMs.
#define XS_STRIDE 80
#define XS_BUF    (768 * XS_STRIDE)       // 61440 B
#define SMEM_TOTAL (2 * XS_BUF)           // 122880 B

__global__ __launch_bounds__(256, 1)
void dcls_mma(const float* __restrict__ bias, float* __restrict__ out) {
    extern __shared__ char smem[];
    const uint32_t sb = smem_u32(smem);

    const int tid  = threadIdx.x;
    const int lane = tid & 31;
    const int warp = tid >> 5;
    const int h    = warp & 1;
    const int r    = warp >> 1;

    const int s  = blockIdx.x;       // 0..887
    const int wt = s & 1;
    const int hg = (s >> 1) % 28;
    const int bb = s / 56;
    const int h0 = hg * 4;
    const int w0 = wt * 56;

    const int bnrow = (lane & 7) + ((lane >> 4) << 3);
    const uint32_t b_lane = (uint32_t)(bnrow * XS_STRIDE + ((lane >> 3) & 1) * 16);

    const char* xtb = (const char*)g_xT + ((size_t)bb * 120 * 120) * 256;

    float acc[4][7][4];
    #pragma unroll
    for (int i = 0; i < 4; i++)
        #pragma unroll
        for (int j = 0; j < 7; j++)
            #pragma unroll
            for (int k = 0; k < 4; k++) acc[i][j][k] = 0.f;

    #define STAGE(c) do {                                                        \
        const uint32_t dstb = sb + ((c) & 1) * XS_BUF;                           \
        _Pragma("unroll")                                                        \
        for (int i_ = 0; i_ < 3; i_++) {                                         \
            int u  = tid + i_ * 256;                                             \
            int hp = h0 + (u >> 6);                                              \
            int wp = w0 + (u & 63);                                              \
            const char* src = xtb + ((size_t)(hp * 120 + wp) << 8) + (c) * 64;   \
            uint32_t dst = dstb + u * XS_STRIDE;                                 \
            CP_ASYNC16(dst,      src);                                           \
            CP_ASYNC16(dst + 16, src + 16);                                      \
            CP_ASYNC16(dst + 32, src + 32);                                      \
            CP_ASYNC16(dst + 48, src + 48);                                      \
        }                                                                        \
        CP_COMMIT();                                                             \
    } while (0)

    STAGE(0);

    for (int c = 0; c < 4; c++) {
        const uint4* Ab = g_K2f + ((size_t)c * 16 + h * 8) * 32 + lane;
        uint4 cur[8], nxt[8];
        #pragma unroll
        for (int t = 0; t < 8; t++) cur[t] = Ab[t * 32];

        CP_WAIT0();
        __syncthreads();
        if (c < 3) STAGE(c + 1);

        const uint32_t xbb = sb + (c & 1) * XS_BUF;
        int dh = 0, dw = 0;
        for (int tap = 0; tap < 81; tap++) {
            if (tap < 80) {
                const uint4* An = Ab + (size_t)(tap + 1) * 2048;
                #pragma unroll
                for (int t = 0; t < 8; t++) nxt[t] = An[t * 32];
            }

            const uint32_t bbase = xbb + (uint32_t)(((r + dh) * 64 + dw) * XS_STRIDE) + b_lane;

            #pragma unroll
            for (int kk = 0; kk < 2; kk++) {
                #pragma unroll
                for (int j2 = 0; j2 < 3; j2++) {
                    uint32_t b[4];
                    LDSM4(b, bbase + j2 * 1280 + kk * 32);
                    #pragma unroll
                    for (int i = 0; i < 4; i++) {
                        const uint32_t* a = reinterpret_cast<const uint32_t*>(&cur[i * 2 + kk]);
                        HMMA(acc[i][2 * j2],     a, b[0], b[1]);
                        HMMA(acc[i][2 * j2 + 1], a, b[2], b[3]);
                    }
                }
                uint32_t b2[2];
                LDSM2(b2, bbase + 3 * 1280 + kk * 32);
                #pragma unroll
                for (int i = 0; i < 4; i++) {
                    const uint32_t* a = reinterpret_cast<const uint32_t*>(&cur[i * 2 + kk]);
                    HMMA(acc[i][6], a, b2[0], b2[1]);
                }
            }

            if (tap < 80) {
                #pragma unroll
                for (int t = 0; t < 8; t++) cur[t] = nxt[t];
            }
            if (++dw == 9) { dw = 0; dh++; }
        }
    }

    const int gq = lane >> 2, tq = lane & 3;
    #pragma unroll
    for (int i = 0; i < 4; i++) {
        const int co = h * 64 + i * 16 + gq;
        const float b0 = bias[co];
        const float b1 = bias[co + 8];
        const size_t o0 = ((size_t)(bb * 128 + co) * 112 + (h0 + r)) * 112 + w0;
        const size_t o1 = o0 + (size_t)8 * 12544;
        #pragma unroll
        for (int j = 0; j < 7; j++) {
            const int wcol = j * 8 + tq * 2;
            *(float2*)(out + o0 + wcol) = make_float2(acc[i][j][0] + b0, acc[i][j][1] + b0);
            *(float2*)(out + o1 + wcol) = make_float2(acc[i][j][2] + b1, acc[i][j][3] + b1);
        }
    }
}

// ================= stage 2b: TAIL (tiles 888..895 as 16 half-tiles) =================
// Block (128 thr, 4 warps = 2 co-halves x 2 rows): 128 co x (2 rows x 56 w).
// Same warp tile & inner loop shape; x tile 10 rows x 64 cols.
#define TXS_BUF (640 * XS_STRIDE)          // 10*64 px = 51200 B
#define TSMEM_TOTAL (2 * TXS_BUF)          // 102400 B

__global__ __launch_bounds__(128, 1)
void dcls_tail(const float* __restrict__ bias, float* __restrict__ out) {
    extern __shared__ char smem[];
    const uint32_t sb = smem_u32(smem);

    const int tid  = threadIdx.x;
    const int lane = tid & 31;
    const int warp = tid >> 5;
    const int h    = warp & 1;       // co half
    const int r    = warp >> 1;      // row within half-tile: 0..1

    const int q    = blockIdx.x;     // 0..15
    const int tile = 888 + (q >> 1);
    const int half = q & 1;
    const int wt = tile & 1;
    const int hg = (tile >> 1) % 28;
    const int bb = tile / 56;
    const int h0 = hg * 4 + half * 2;   // first of this half's 2 rows
    const int w0 = wt * 56;

    const int bnrow = (lane & 7) + ((lane >> 4) << 3);
    const uint32_t b_lane = (uint32_t)(bnrow * XS_STRIDE + ((lane >> 3) & 1) * 16);

    const char* xtb = (const char*)g_xT + ((size_t)bb * 120 * 120) * 256;

    float acc[4][7][4];
    #pragma unroll
    for (int i = 0; i < 4; i++)
        #pragma unroll
        for (int j = 0; j < 7; j++)
            #pragma unroll
            for (int k = 0; k < 4; k++) acc[i][j][k] = 0.f;

    // stage: 10 rows x 64 cols = 640 px; 128 thr x 5 px x 4 cp.async16
    #define TSTAGE(c) do {                                                       \
        const uint32_t dstb = sb + ((c) & 1) * TXS_BUF;                          \
        _Pragma("unroll")                                                        \
        for (int i_ = 0; i_ < 5; i_++) {                                         \
            int u  = tid + i_ * 128;           /* pixel 0..639 */                \
            int hp = h0 + (u >> 6);                                              \
            int wp = w0 + (u & 63);                                              \
            const char* src = xtb + ((size_t)(hp * 120 + wp) << 8) + (c) * 64;   \
            uint32_t dst = dstb + u * XS_STRIDE;                                 \
            CP_ASYNC16(dst,      src);                                           \
            CP_ASYNC16(dst + 16, src + 16);                                      \
            CP_ASYNC16(dst + 32, src + 32);                                      \
            CP_ASYNC16(dst + 48, src + 48);                                      \
        }                                                                        \
        CP_COMMIT();                                                             \
    } while (0)

    TSTAGE(0);

    for (int c = 0; c < 4; c++) {
        const uint4* Ab = g_K2f + ((size_t)c * 16 + h * 8) * 32 + lane;
        uint4 cur[8], nxt[8];
        #pragma unroll
        for (int t = 0; t < 8; t++) cur[t] = Ab[t * 32];

        CP_WAIT0();
        __syncthreads();
        if (c < 3) TSTAGE(c + 1);

        const uint32_t xbb = sb + (c & 1) * TXS_BUF;
        int dh = 0, dw = 0;
        for (int tap = 0; tap < 81; tap++) {
            if (tap < 80) {
                const uint4* An = Ab + (size_t)(tap + 1) * 2048;
                #pragma unroll
                for (int t = 0; t < 8; t++) nxt[t] = An[t * 32];
            }

            const uint32_t bbase = xbb + (uint32_t)(((r + dh) * 64 + dw) * XS_STRIDE) + b_lane;

            #pragma unroll
            for (int kk = 0; kk < 2; kk++) {
                #pragma unroll
                for (int j2 = 0; j2 < 3; j2++) {
                    uint32_t b[4];
                    LDSM4(b, bbase + j2 * 1280 + kk * 32);
                    #pragma unroll
                    for (int i = 0; i < 4; i++) {
                        const uint32_t* a = reinterpret_cast<const uint32_t*>(&cur[i * 2 + kk]);
                        HMMA(acc[i][2 * j2],     a, b[0], b[1]);
                        HMMA(acc[i][2 * j2 + 1], a, b[2], b[3]);
                    }
                }
                uint32_t b2[2];
                LDSM2(b2, bbase + 3 * 1280 + kk * 32);
                #pragma unroll
                for (int i = 0; i < 4; i++) {
                    const uint32_t* a = reinterpret_cast<const uint32_t*>(&cur[i * 2 + kk]);
                    HMMA(acc[i][6], a, b2[0], b2[1]);
                }
            }

            if (tap < 80) {
                #pragma unroll
                for (int t = 0; t < 8; t++) cur[t] = nxt[t];
            }
            if (++dw == 9) { dw = 0; dh++; }
        }
    }

    const int gq = lane >> 2, tq = lane & 3;
    #pragma unroll
    for (int i = 0; i < 4; i++) {
        const int co = h * 64 + i * 16 + gq;
        const float b0 = bias[co];
        const float b1 = bias[co + 8];
        const size_t o0 = ((size_t)(bb * 128 + co) * 112 + (h0 + r)) * 112 + w0;
        const size_t o1 = o0 + (size_t)8 * 12544;
        #pragma unroll
        for (int j = 0; j < 7; j++) {
            const int wcol = j * 8 + tq * 2;
            *(float2*)(out + o0 + wcol) = make_float2(acc[i][j][0] + b0, acc[i][j][1] + b0);
            *(float2*)(out + o1 + wcol) = make_float2(acc[i][j][2] + b1, acc[i][j][3] + b1);
        }
    }
}

// ================= launch =================
extern "C" void kernel_launch(void* const* d_in, const int* in_sizes, int n_in,
                              void* d_out, int out_size) {
    const float* x      = (const float*)d_in[0];
    const float* weight = (const float*)d_in[1];
    const float* P      = (const float*)d_in[2];
    const float* bias   = (const float*)d_in[3];
    float* out = (float*)d_out;

    prep<<<2048, 256, 41472>>>(x, weight, P);

    cudaFuncSetAttribute(dcls_mma, cudaFuncAttributeMaxDynamicSharedMemorySize, SMEM_TOTAL);
    dcls_mma<<<888, 256, SMEM_TOTAL>>>(bias, out);

    cudaFuncSetAttribute(dcls_tail, cudaFuncAttributeMaxDynamicSharedMemorySize, TSMEM_TOTAL);
    dcls_tail<<<16, 128, TSMEM_TOTAL>>>(bias, out);
}

// round 16
// speedup vs baseline: 1.1081x; 1.1081x over previous
#include <cuda_runtime.h>
#include <cuda_fp16.h>
#include <cstdint>
#include <cstddef>

// ================= problem =================
// x:(16,128,112,112)f32  weight:(128,128,3,3)  P:(2,128,128,3,3)  bias:(128)
// out:(16,128,112,112) = conv(x, scatter(weight,P) 9x9, pad 4) + bias

#define TAPS 81

// K2 fragment layout: [tap][cichunk(4)][cotile16(8)][kk(2)][lane(32)] uint4
// (2048 uint4 / tap). Lane's uint4 = m16k16 fp16 A-frag regs {a0,a1,a2,a3}:
//   lane=(row&7)*4+((col&7)>>1), reg=(row>>3)+((col>>3)<<1), half=(col&1)
__device__ uint4 g_K2f[TAPS * 4 * 8 * 2 * 32];

// x transposed to f16 NHWC with baked-in halo: [b][h+4 (120)][w+4 (120)][ci 128]
__device__ uint4 g_xT[16 * 120 * 120 * 128 / 8];

__device__ __forceinline__ uint32_t smem_u32(const void* p) {
    uint32_t a;
    asm("{ .reg .u64 t; cvta.to.shared.u64 t, %1; cvt.u32.u64 %0, t; }" : "=r"(a) : "l"(p));
    return a;
}

#define LDSM4(rv, addr)                                                          \
    asm volatile("ldmatrix.sync.aligned.m8n8.x4.shared.b16 {%0,%1,%2,%3}, [%4];" \
        : "=r"((rv)[0]), "=r"((rv)[1]), "=r"((rv)[2]), "=r"((rv)[3]) : "r"(addr))

#define LDSM2(rv, addr)                                                      \
    asm volatile("ldmatrix.sync.aligned.m8n8.x2.shared.b16 {%0,%1}, [%2];"   \
        : "=r"((rv)[0]), "=r"((rv)[1]) : "r"(addr))

#define HMMA(d, a, b0, b1)                                                   \
    asm volatile("mma.sync.aligned.m16n8k16.row.col.f32.f16.f16.f32 "        \
        "{%0,%1,%2,%3}, {%4,%5,%6,%7}, {%8,%9}, {%0,%1,%2,%3};"              \
        : "+f"((d)[0]), "+f"((d)[1]), "+f"((d)[2]), "+f"((d)[3])             \
        : "r"((a)[0]), "r"((a)[1]), "r"((a)[2]), "r"((a)[3]),                \
          "r"(b0), "r"(b1))

#define CP_ASYNC16(sdst, gsrc)                                               \
    asm volatile("cp.async.cg.shared.global [%0], [%1], 16;"                 \
        :: "r"(sdst), "l"(gsrc) : "memory")
#define CP_COMMIT()   asm volatile("cp.async.commit_group;" ::: "memory")
#define CP_WAIT0()    asm volatile("cp.async.wait_group 0;" ::: "memory")

// ======== merged pre-pass: transpose x -> f16 NHWC (halo zeroed) + build_K ========
// grid 2048: blocks 0..1919 transpose (b = blk/120, hp = blk%120);
//            blocks 1920..2047 scatter weights for co = blk-1920.
// Dynamic smem reused by both paths (41472 B). Measured 40 us (round 15).
__global__ void prep(const float* __restrict__ x,
                     const float* __restrict__ weight, const float* __restrict__ P) {
    extern __shared__ char psm[];
    const int tid = threadIdx.x;

    if (blockIdx.x < 1920) {
        __half* s = (__half*)psm;              // [112][130]
        const int b  = blockIdx.x / 120;
        const int hp = blockIdx.x - b * 120;
        __half* xt = (__half*)g_xT + (((size_t)b * 120 + hp) * 120) * 128;

        if (hp < 4 || hp >= 116) {             // full halo row
            uint4 z = make_uint4(0, 0, 0, 0);
            for (int u = tid; u < 1920; u += 256) ((uint4*)xt)[u] = z;
            return;
        }
        const int hh = hp - 4;

        const float* xb = x + ((size_t)b * 128) * 12544 + hh * 112;
        for (int u = tid; u < 128 * 112; u += 256) {
            int ci = u / 112, w = u - ci * 112;
            s[w * 130 + ci] = __float2half_rn(xb[(size_t)ci * 12544 + w]);
        }
        {   // w halo: pixels 0..3 and 116..119
            uint4 z = make_uint4(0, 0, 0, 0);
            for (int u = tid; u < 128; u += 256) {
                int side = u >> 6, pw = (u >> 4) & 3, seg = u & 15;
                ((uint4*)(xt + (size_t)(side * 116 + pw) * 128))[seg] = z;
            }
        }
        __syncthreads();

        __half* xti = xt + 4 * 128;
        for (int u = tid; u < 112 * 64; u += 256) {
            int w = u >> 6, cp = u & 63;
            __half2 v = make_half2(s[w * 130 + 2 * cp], s[w * 130 + 2 * cp + 1]);
            *(__half2*)(xti + (size_t)w * 128 + 2 * cp) = v;
        }
        return;
    }

    // ---- build_K path ----
    if (tid >= 128) return;
    float (*sK)[81] = (float(*)[81])psm;       // [128][81]
    const int co = blockIdx.x - 1920;
    const int ci = tid;

    #pragma unroll
    for (int i = 0; i < 81; i++) sK[ci][i] = 0.f;

    const float* P0 = P;
    const float* P1 = P + 128 * 128 * 9;

    #pragma unroll
    for (int kh = 0; kh < 3; kh++) {
        #pragma unroll
        for (int kw = 0; kw < 3; kw++) {
            int widx = ((co * 128 + ci) * 3 + kh) * 3 + kw;
            float w  = weight[widx];
            float ph = (float)(kh * 4) + P0[widx];
            float pw = (float)(kw * 4) + P1[widx];
            ph = fminf(fmaxf(ph, 0.f), 8.f);
            pw = fminf(fmaxf(pw, 0.f), 8.f);
            float fh = floorf(ph), fw = floorf(pw);
            float rh = ph - fh,    rw = pw - fw;
            int ih = (int)fh, iw = (int)fw;
            int ih1 = min(ih + 1, 8), iw1 = min(iw + 1, 8);
            sK[ci][ih  * 9 + iw ] += w * (1.f - rh) * (1.f - rw);
            sK[ci][ih1 * 9 + iw ] += w * rh         * (1.f - rw);
            sK[ci][ih  * 9 + iw1] += w * (1.f - rh) * rw;
            sK[ci][ih1 * 9 + iw1] += w * rh         * rw;
        }
    }
    __syncwarp();

    const int c     = ci >> 5;
    const int kk    = (ci >> 4) & 1;
    const int col   = ci & 15;
    const int iglob = co >> 4;
    const int row   = co & 15;
    const int lane  = (row & 7) * 4 + ((col & 7) >> 1);
    const int reg   = (row >> 3) + ((col >> 3) << 1);
    __half* gh = (__half*)g_K2f;
    const size_t slot = ((((size_t)c * 8 + iglob) * 2 + kk) * 32 + lane) * 8 + reg * 2 + (col & 1);
    for (int tap = 0; tap < 81; tap++)
        gh[(size_t)tap * 16384 + slot] = __float2half_rn(sK[ci][tap]);
}

// ================= stage 2: fp16 implicit-GEMM conv =================
// EXACT round-10 structure (best measured: mma ~1035 us, tensor ~81%):
//   Block: 128 co x (4 rows x 56 w). 8 warps = 2 co-halves(64) x 4 rows.
//   Warp tile: 64co x 56px = 4 m-frags x 7 n-frags. K = ci, 4 chunks of 32.
//   A: fragment-layout LDG, register double-buffered (448-cyc chains cover L2).
//   B: x tile via cp.async from f16 NHWC xT, double-buffered across chunks.
// Grid 896 on 152 SMs = 6 waves, last wave 136/152 (~2% tail loss only).
#define XS_STRIDE 80
#define XS_BUF    (768 * XS_STRIDE)       // 12 rows x 64 cols pixels = 61440 B
#define SMEM_TOTAL (2 * XS_BUF)           // 122880 B

__global__ __launch_bounds__(256, 1)
void dcls_mma(const float* __restrict__ bias, float* __restrict__ out) {
    extern __shared__ char smem[];
    const uint32_t sb = smem_u32(smem);

    const int tid  = threadIdx.x;
    const int lane = tid & 31;
    const int warp = tid >> 5;
    const int h    = warp & 1;       // co half (64) within block
    const int r    = warp >> 1;      // output row 0..3

    const int s  = blockIdx.x;       // 0..895
    const int wt = s & 1;
    const int hg = (s >> 1) % 28;
    const int bb = s / 56;
    const int h0 = hg * 4;
    const int w0 = wt * 56;

    // ldmatrix B lane offset
    const int bnrow = (lane & 7) + ((lane >> 4) << 3);
    const uint32_t b_lane = (uint32_t)(bnrow * XS_STRIDE + ((lane >> 3) & 1) * 16);

    const char* xtb = (const char*)g_xT + ((size_t)bb * 120 * 120) * 256;

    float acc[4][7][4];
    #pragma unroll
    for (int i = 0; i < 4; i++)
        #pragma unroll
        for (int j = 0; j < 7; j++)
            #pragma unroll
            for (int k = 0; k < 4; k++) acc[i][j][k] = 0.f;

    // stage x chunk c (32 ci = 64 B/pixel) into buffer c&1: 12 cp.async/thread
    #define STAGE(c) do {                                                        \
        const uint32_t dstb = sb + ((c) & 1) * XS_BUF;                           \
        _Pragma("unroll")                                                        \
        for (int i_ = 0; i_ < 3; i_++) {                                         \
            int u  = tid + i_ * 256;           /* pixel 0..767 */                \
            int hp = h0 + (u >> 6);                                              \
            int wp = w0 + (u & 63);                                              \
            const char* src = xtb + ((size_t)(hp * 120 + wp) << 8) + (c) * 64;   \
            uint32_t dst = dstb + u * XS_STRIDE;                                 \
            CP_ASYNC16(dst,      src);                                           \
            CP_ASYNC16(dst + 16, src + 16);                                      \
            CP_ASYNC16(dst + 32, src + 32);                                      \
            CP_ASYNC16(dst + 48, src + 48);                                      \
        }                                                                        \
        CP_COMMIT();                                                             \
    } while (0)

    STAGE(0);

    for (int c = 0; c < 4; c++) {
        // first A frags of this chunk (pure global, overlaps the wait)
        const uint4* Ab = g_K2f + ((size_t)c * 16 + h * 8) * 32 + lane;
        uint4 cur[8], nxt[8];
        #pragma unroll
        for (int t = 0; t < 8; t++) cur[t] = Ab[t * 32];

        CP_WAIT0();          // chunk c's x tile landed
        __syncthreads();     // publish + previous chunk's readers are done
        if (c < 3) STAGE(c + 1);   // stream next chunk under this compute

        const uint32_t xbb = sb + (c & 1) * XS_BUF;
        int dh = 0, dw = 0;
        for (int tap = 0; tap < 81; tap++) {
            if (tap < 80) {
                const uint4* An = Ab + (size_t)(tap + 1) * 2048;
                #pragma unroll
                for (int t = 0; t < 8; t++) nxt[t] = An[t * 32];
            }

            const uint32_t bbase = xbb + (uint32_t)(((r + dh) * 64 + dw) * XS_STRIDE) + b_lane;

            #pragma unroll
            for (int kk = 0; kk < 2; kk++) {
                #pragma unroll
                for (int j2 = 0; j2 < 3; j2++) {
                    uint32_t b[4];
                    LDSM4(b, bbase + j2 * 1280 + kk * 32);
                    #pragma unroll
                    for (int i = 0; i < 4; i++) {
                        const uint32_t* a = reinterpret_cast<const uint32_t*>(&cur[i * 2 + kk]);
                        HMMA(acc[i][2 * j2],     a, b[0], b[1]);
                        HMMA(acc[i][2 * j2 + 1], a, b[2], b[3]);
                    }
                }
                uint32_t b2[2];
                LDSM2(b2, bbase + 3 * 1280 + kk * 32);
                #pragma unroll
                for (int i = 0; i < 4; i++) {
                    const uint32_t* a = reinterpret_cast<const uint32_t*>(&cur[i * 2 + kk]);
                    HMMA(acc[i][6], a, b2[0], b2[1]);
                }
            }

            if (tap < 80) {
                #pragma unroll
                for (int t = 0; t < 8; t++) cur[t] = nxt[t];
            }
            if (++dw == 9) { dw = 0; dh++; }
        }
    }

    // ================= epilogue: + bias, float2 stores =================
    const int gq = lane >> 2, tq = lane & 3;
    #pragma unroll
    for (int i = 0; i < 4; i++) {
        const int co = h * 64 + i * 16 + gq;
        const float b0 = bias[co];
        const float b1 = bias[co + 8];
        const size_t o0 = ((size_t)(bb * 128 + co) * 112 + (h0 + r)) * 112 + w0;
        const size_t o1 = o0 + (size_t)8 * 12544;
        #pragma unroll
        for (int j = 0; j < 7; j++) {
            const int wcol = j * 8 + tq * 2;
            *(float2*)(out + o0 + wcol) = make_float2(acc[i][j][0] + b0, acc[i][j][1] + b0);
            *(float2*)(out + o1 + wcol) = make_float2(acc[i][j][2] + b1, acc[i][j][3] + b1);
        }
    }
}

// ================= launch =================
extern "C" void kernel_launch(void* const* d_in, const int* in_sizes, int n_in,
                              void* d_out, int out_size) {
    const float* x      = (const float*)d_in[0];
    const float* weight = (const float*)d_in[1];
    const float* P      = (const float*)d_in[2];
    const float* bias   = (const float*)d_in[3];
    float* out = (float*)d_out;

    prep<<<2048, 256, 41472>>>(x, weight, P);

    cudaFuncSetAttribute(dcls_mma, cudaFuncAttributeMaxDynamicSharedMemorySize, SMEM_TOTAL);
    dcls_mma<<<896, 256, SMEM_TOTAL>>>(bias, out);
}

// round 17
// speedup vs baseline: 1.1764x; 1.0616x over previous
#include <cuda_runtime.h>
#include <cuda_fp16.h>
#include <cstdint>
#include <cstddef>

// ================= problem =================
// x:(16,128,112,112)f32  weight:(128,128,3,3)  P:(2,128,128,3,3)  bias:(128)
// out:(16,128,112,112) = conv(x, scatter(weight,P) 9x9, pad 4) + bias

#define TAPS 81

// K2 fragment layout: [tap][cichunk(4)][cotile16(8)][kk(2)][lane(32)] uint4
// (2048 uint4 / tap). Lane's uint4 = m16k16 fp16 A-frag regs {a0,a1,a2,a3}:
//   lane=(row&7)*4+((col&7)>>1), reg=(row>>3)+((col>>3)<<1), half=(col&1)
__device__ uint4 g_K2f[TAPS * 4 * 8 * 2 * 32];

// x transposed to f16 NHWC with baked-in halo: [b][h+4 (120)][w+4 (120)][ci 128]
__device__ uint4 g_xT[16 * 120 * 120 * 128 / 8];

__device__ __forceinline__ uint32_t smem_u32(const void* p) {
    uint32_t a;
    asm("{ .reg .u64 t; cvta.to.shared.u64 t, %1; cvt.u32.u64 %0, t; }" : "=r"(a) : "l"(p));
    return a;
}

#define LDSM4(rv, addr)                                                          \
    asm volatile("ldmatrix.sync.aligned.m8n8.x4.shared.b16 {%0,%1,%2,%3}, [%4];" \
        : "=r"((rv)[0]), "=r"((rv)[1]), "=r"((rv)[2]), "=r"((rv)[3]) : "r"(addr))

#define LDSM2(rv, addr)                                                      \
    asm volatile("ldmatrix.sync.aligned.m8n8.x2.shared.b16 {%0,%1}, [%2];"   \
        : "=r"((rv)[0]), "=r"((rv)[1]) : "r"(addr))

#define HMMA(d, a, b0, b1)                                                   \
    asm volatile("mma.sync.aligned.m16n8k16.row.col.f32.f16.f16.f32 "        \
        "{%0,%1,%2,%3}, {%4,%5,%6,%7}, {%8,%9}, {%0,%1,%2,%3};"              \
        : "+f"((d)[0]), "+f"((d)[1]), "+f"((d)[2]), "+f"((d)[3])             \
        : "r"((a)[0]), "r"((a)[1]), "r"((a)[2]), "r"((a)[3]),                \
          "r"(b0), "r"(b1))

#define CP_ASYNC16(sdst, gsrc)                                               \
    asm volatile("cp.async.cg.shared.global [%0], [%1], 16;"                 \
        :: "r"(sdst), "l"(gsrc) : "memory")
#define CP_COMMIT()   asm volatile("cp.async.commit_group;" ::: "memory")
#define CP_WAIT0()    asm volatile("cp.async.wait_group 0;" ::: "memory")

// ======== merged pre-pass: transpose x -> f16 NHWC (halo zeroed) + build_K ========
// grid 2048: blocks 0..1919 transpose (b = blk/120, hp = blk%120);
//            blocks 1920..2047 scatter weights for co = blk-1920.
// Dynamic smem reused by both paths (41472 B). Measured 40 us.
__global__ void prep(const float* __restrict__ x,
                     const float* __restrict__ weight, const float* __restrict__ P) {
    extern __shared__ char psm[];
    const int tid = threadIdx.x;

    if (blockIdx.x < 1920) {
        __half* s = (__half*)psm;              // [112][130]
        const int b  = blockIdx.x / 120;
        const int hp = blockIdx.x - b * 120;
        __half* xt = (__half*)g_xT + (((size_t)b * 120 + hp) * 120) * 128;

        if (hp < 4 || hp >= 116) {             // full halo row
            uint4 z = make_uint4(0, 0, 0, 0);
            for (int u = tid; u < 1920; u += 256) ((uint4*)xt)[u] = z;
            return;
        }
        const int hh = hp - 4;

        const float* xb = x + ((size_t)b * 128) * 12544 + hh * 112;
        for (int u = tid; u < 128 * 112; u += 256) {
            int ci = u / 112, w = u - ci * 112;
            s[w * 130 + ci] = __float2half_rn(xb[(size_t)ci * 12544 + w]);
        }
        {   // w halo: pixels 0..3 and 116..119
            uint4 z = make_uint4(0, 0, 0, 0);
            for (int u = tid; u < 128; u += 256) {
                int side = u >> 6, pw = (u >> 4) & 3, seg = u & 15;
                ((uint4*)(xt + (size_t)(side * 116 + pw) * 128))[seg] = z;
            }
        }
        __syncthreads();

        __half* xti = xt + 4 * 128;
        for (int u = tid; u < 112 * 64; u += 256) {
            int w = u >> 6, cp = u & 63;
            __half2 v = make_half2(s[w * 130 + 2 * cp], s[w * 130 + 2 * cp + 1]);
            *(__half2*)(xti + (size_t)w * 128 + 2 * cp) = v;
        }
        return;
    }

    // ---- build_K path ----
    if (tid >= 128) return;
    float (*sK)[81] = (float(*)[81])psm;       // [128][81]
    const int co = blockIdx.x - 1920;
    const int ci = tid;

    #pragma unroll
    for (int i = 0; i < 81; i++) sK[ci][i] = 0.f;

    const float* P0 = P;
    const float* P1 = P + 128 * 128 * 9;

    #pragma unroll
    for (int kh = 0; kh < 3; kh++) {
        #pragma unroll
        for (int kw = 0; kw < 3; kw++) {
            int widx = ((co * 128 + ci) * 3 + kh) * 3 + kw;
            float w  = weight[widx];
            float ph = (float)(kh * 4) + P0[widx];
            float pw = (float)(kw * 4) + P1[widx];
            ph = fminf(fmaxf(ph, 0.f), 8.f);
            pw = fminf(fmaxf(pw, 0.f), 8.f);
            float fh = floorf(ph), fw = floorf(pw);
            float rh = ph - fh,    rw = pw - fw;
            int ih = (int)fh, iw = (int)fw;
            int ih1 = min(ih + 1, 8), iw1 = min(iw + 1, 8);
            sK[ci][ih  * 9 + iw ] += w * (1.f - rh) * (1.f - rw);
            sK[ci][ih1 * 9 + iw ] += w * rh         * (1.f - rw);
            sK[ci][ih  * 9 + iw1] += w * (1.f - rh) * rw;
            sK[ci][ih1 * 9 + iw1] += w * rh         * rw;
        }
    }
    __syncwarp();

    const int c     = ci >> 5;
    const int kk    = (ci >> 4) & 1;
    const int col   = ci & 15;
    const int iglob = co >> 4;
    const int row   = co & 15;
    const int lane  = (row & 7) * 4 + ((col & 7) >> 1);
    const int reg   = (row >> 3) + ((col >> 3) << 1);
    __half* gh = (__half*)g_K2f;
    const size_t slot = ((((size_t)c * 8 + iglob) * 2 + kk) * 32 + lane) * 8 + reg * 2 + (col & 1);
    for (int tap = 0; tap < 81; tap++)
        gh[(size_t)tap * 16384 + slot] = __float2half_rn(sK[ci][tap]);
}

// ================= stage 2: fp16 implicit-GEMM conv =================
// Round-16 structure with the tap loop unrolled by 2 and alternating A buffers
// (no cur<-nxt register copies; prefetch-wait folds into first dependent HMMA):
//   Block: 128 co x (4 rows x 56 w). 8 warps = 2 co-halves(64) x 4 rows.
//   Warp tile: 64co x 56px = 4 m-frags x 7 n-frags. K = ci, 4 chunks of 32.
//   A: fragment-layout LDG, two alternating register buffers.
//   B: x tile via cp.async from f16 NHWC xT, double-buffered across chunks.
#define XS_STRIDE 80
#define XS_BUF    (768 * XS_STRIDE)       // 61440 B
#define SMEM_TOTAL (2 * XS_BUF)           // 122880 B

__global__ __launch_bounds__(256, 1)
void dcls_mma(const float* __restrict__ bias, float* __restrict__ out) {
    extern __shared__ char smem[];
    const uint32_t sb = smem_u32(smem);

    const int tid  = threadIdx.x;
    const int lane = tid & 31;
    const int warp = tid >> 5;
    const int h    = warp & 1;       // co half (64) within block
    const int r    = warp >> 1;      // output row 0..3

    const int s  = blockIdx.x;       // 0..895
    const int wt = s & 1;
    const int hg = (s >> 1) % 28;
    const int bb = s / 56;
    const int h0 = hg * 4;
    const int w0 = wt * 56;

    const int bnrow = (lane & 7) + ((lane >> 4) << 3);
    const uint32_t b_lane = (uint32_t)(bnrow * XS_STRIDE + ((lane >> 3) & 1) * 16);

    const char* xtb = (const char*)g_xT + ((size_t)bb * 120 * 120) * 256;

    float acc[4][7][4];
    #pragma unroll
    for (int i = 0; i < 4; i++)
        #pragma unroll
        for (int j = 0; j < 7; j++)
            #pragma unroll
            for (int k = 0; k < 4; k++) acc[i][j][k] = 0.f;

    #define STAGE(c) do {                                                        \
        const uint32_t dstb = sb + ((c) & 1) * XS_BUF;                           \
        _Pragma("unroll")                                                        \
        for (int i_ = 0; i_ < 3; i_++) {                                         \
            int u  = tid + i_ * 256;           /* pixel 0..767 */                \
            int hp = h0 + (u >> 6);                                              \
            int wp = w0 + (u & 63);                                              \
            const char* src = xtb + ((size_t)(hp * 120 + wp) << 8) + (c) * 64;   \
            uint32_t dst = dstb + u * XS_STRIDE;                                 \
            CP_ASYNC16(dst,      src);                                           \
            CP_ASYNC16(dst + 16, src + 16);                                      \
            CP_ASYNC16(dst + 32, src + 32);                                      \
            CP_ASYNC16(dst + 48, src + 48);                                      \
        }                                                                        \
        CP_COMMIT();                                                             \
    } while (0)

    // one tap's MMA work using A-fragment buffer `buf`, tap position (dh,dw)
    #define TAP_MMA(buf, dh, dw) do {                                            \
        const uint32_t bbase = xbb                                               \
            + (uint32_t)((((r) + (dh)) * 64 + (dw)) * XS_STRIDE) + b_lane;       \
        _Pragma("unroll")                                                        \
        for (int kk = 0; kk < 2; kk++) {                                         \
            _Pragma("unroll")                                                    \
            for (int j2 = 0; j2 < 3; j2++) {                                     \
                uint32_t b[4];                                                   \
                LDSM4(b, bbase + j2 * 1280 + kk * 32);                           \
                _Pragma("unroll")                                                \
                for (int i = 0; i < 4; i++) {                                    \
                    const uint32_t* a =                                          \
                        reinterpret_cast<const uint32_t*>(&(buf)[i * 2 + kk]);   \
                    HMMA(acc[i][2 * j2],     a, b[0], b[1]);                     \
                    HMMA(acc[i][2 * j2 + 1], a, b[2], b[3]);                     \
                }                                                                \
            }                                                                    \
            uint32_t b2[2];                                                      \
            LDSM2(b2, bbase + 3 * 1280 + kk * 32);                               \
            _Pragma("unroll")                                                    \
            for (int i = 0; i < 4; i++) {                                        \
                const uint32_t* a =                                              \
                    reinterpret_cast<const uint32_t*>(&(buf)[i * 2 + kk]);       \
                HMMA(acc[i][6], a, b2[0], b2[1]);                                \
            }                                                                    \
        }                                                                        \
    } while (0)

    #define PREFETCH(buf, tapn) do {                                             \
        const uint4* An = Ab + (size_t)(tapn) * 2048;                            \
        _Pragma("unroll")                                                        \
        for (int t = 0; t < 8; t++) (buf)[t] = An[t * 32];                       \
    } while (0)

    STAGE(0);

    for (int c = 0; c < 4; c++) {
        const uint4* Ab = g_K2f + ((size_t)c * 16 + h * 8) * 32 + lane;
        uint4 bufA[8], bufB[8];
        PREFETCH(bufA, 0);                 // tap 0 (pure global, overlaps wait)

        CP_WAIT0();          // chunk c's x tile landed
        __syncthreads();     // publish + previous chunk's readers are done
        if (c < 3) STAGE(c + 1);   // stream next chunk under this compute

        const uint32_t xbb = sb + (c & 1) * XS_BUF;

        // 81 taps = 40 unrolled pairs + final tap. Buffers alternate:
        // even tap consumes bufA (prefetches bufB), odd consumes bufB.
        int dh = 0, dw = 0;
        #pragma unroll 1
        for (int tp = 0; tp < 40; tp++) {
            const int tap = 2 * tp;
            PREFETCH(bufB, tap + 1);
            TAP_MMA(bufA, dh, dw);
            if (++dw == 9) { dw = 0; dh++; }

            PREFETCH(bufA, tap + 2);
            TAP_MMA(bufB, dh, dw);
            if (++dw == 9) { dw = 0; dh++; }
        }
        TAP_MMA(bufA, dh, dw);             // tap 80 (dh=8, dw=8)
    }

    // ================= epilogue: + bias, float2 stores =================
    const int gq = lane >> 2, tq = lane & 3;
    #pragma unroll
    for (int i = 0; i < 4; i++) {
        const int co = h * 64 + i * 16 + gq;
        const float b0 = bias[co];
        const float b1 = bias[co + 8];
        const size_t o0 = ((size_t)(bb * 128 + co) * 112 + (h0 + r)) * 112 + w0;
        const size_t o1 = o0 + (size_t)8 * 12544;
        #pragma unroll
        for (int j = 0; j < 7; j++) {
            const int wcol = j * 8 + tq * 2;
            *(float2*)(out + o0 + wcol) = make_float2(acc[i][j][0] + b0, acc[i][j][1] + b0);
            *(float2*)(out + o1 + wcol) = make_float2(acc[i][j][2] + b1, acc[i][j][3] + b1);
        }
    }
}

// ================= launch =================
extern "C" void kernel_launch(void* const* d_in, const int* in_sizes, int n_in,
                              void* d_out, int out_size) {
    const float* x      = (const float*)d_in[0];
    const float* weight = (const float*)d_in[1];
    const float* P      = (const float*)d_in[2];
    const float* bias   = (const float*)d_in[3];
    float* out = (float*)d_out;

    prep<<<2048, 256, 41472>>>(x, weight, P);

    cudaFuncSetAttribute(dcls_mma, cudaFuncAttributeMaxDynamicSharedMemorySize, SMEM_TOTAL);
    dcls_mma<<<896, 256, SMEM_TOTAL>>>(bias, out);
}